// round 12
// baseline (speedup 1.0000x reference)
#include <cuda_runtime.h>

#define N_NODES 50000
#define N_EDGES 800000
#define HIDDEN 64
#define OUT_DIM 16
#define NBLK 444          // 3 blocks/SM x 148 SMs
#define TPB 256
#define GSTRIDE (NBLK * TPB)
#define CHUNK 113         // ceil(50000/444)
#define TILE_N 64
#define NTILES 782        // ceil(50000/64)
#define SROW 132          // padded feature row: 128 data + 4 pad

// ---------------- device scratch ----------------
__device__ int g_count[N_NODES];
__device__ int g_off[N_NODES + 1];
__device__ int g_csr[N_EDGES];
__device__ int g_blocksum[NBLK];
__device__ int g_blockoff[NBLK];
__device__ unsigned g_bar_cnt;
__device__ unsigned g_bar_gen;
__device__ __align__(16) float g_h0[N_NODES * HIDDEN];
__device__ __align__(16) float g_h1[N_NODES * HIDDEN];

// ---------------- software grid barrier ----------------
__device__ __forceinline__ void grid_barrier() {
    __syncthreads();
    if (threadIdx.x == 0) {
        unsigned gen = *((volatile unsigned*)&g_bar_gen);
        __threadfence();
        unsigned a = atomicAdd(&g_bar_cnt, 1u);
        if (a == NBLK - 1) {
            g_bar_cnt = 0;
            __threadfence();
            atomicExch(&g_bar_gen, gen + 1u);
        } else {
            while (*((volatile unsigned*)&g_bar_gen) == gen) { __nanosleep(32); }
        }
        __threadfence();
    }
    __syncthreads();
}

__device__ __forceinline__ float4 fma4(float s, float4 w, float4 acc) {
    acc.x = fmaf(s, w.x, acc.x);
    acc.y = fmaf(s, w.y, acc.y);
    acc.z = fmaf(s, w.z, acc.z);
    acc.w = fmaf(s, w.w, acc.w);
    return acc;
}
__device__ __forceinline__ float4 relu4(float4 v) {
    v.x = fmaxf(v.x, 0.f); v.y = fmaxf(v.y, 0.f);
    v.z = fmaxf(v.z, 0.f); v.w = fmaxf(v.w, 0.f);
    return v;
}
__device__ __forceinline__ void acc4(float4& a, float4 v) {
    a.x += v.x; a.y += v.y; a.z += v.z; a.w += v.w;
}

// ---------------- gather-mean: 8 rows in flight, rows L2-streamed ----------------
__device__ __forceinline__ float4 gather_mean(const float4* __restrict__ x4,
                                              int node, int q) {
    int s = __ldg(&g_off[node]);
    int e = __ldg(&g_off[node + 1]);
    float4 acc = make_float4(0.f, 0.f, 0.f, 0.f);
    int i = s;
    int j0 = 0, j1 = 0, j2 = 0, j3 = 0, j4 = 0, j5 = 0, j6 = 0, j7 = 0;
    if (i + 8 <= e) {
        j0 = __ldg(&g_csr[i]);     j1 = __ldg(&g_csr[i + 1]);
        j2 = __ldg(&g_csr[i + 2]); j3 = __ldg(&g_csr[i + 3]);
        j4 = __ldg(&g_csr[i + 4]); j5 = __ldg(&g_csr[i + 5]);
        j6 = __ldg(&g_csr[i + 6]); j7 = __ldg(&g_csr[i + 7]);
    }
    while (i + 8 <= e) {
        float4 v0 = __ldcg(&x4[j0 * 16 + q]);
        float4 v1 = __ldcg(&x4[j1 * 16 + q]);
        float4 v2 = __ldcg(&x4[j2 * 16 + q]);
        float4 v3 = __ldcg(&x4[j3 * 16 + q]);
        float4 v4 = __ldcg(&x4[j4 * 16 + q]);
        float4 v5 = __ldcg(&x4[j5 * 16 + q]);
        float4 v6 = __ldcg(&x4[j6 * 16 + q]);
        float4 v7 = __ldcg(&x4[j7 * 16 + q]);
        i += 8;
        if (i + 8 <= e) {
            j0 = __ldg(&g_csr[i]);     j1 = __ldg(&g_csr[i + 1]);
            j2 = __ldg(&g_csr[i + 2]); j3 = __ldg(&g_csr[i + 3]);
            j4 = __ldg(&g_csr[i + 4]); j5 = __ldg(&g_csr[i + 5]);
            j6 = __ldg(&g_csr[i + 6]); j7 = __ldg(&g_csr[i + 7]);
        }
        acc4(acc, v0); acc4(acc, v1); acc4(acc, v2); acc4(acc, v3);
        acc4(acc, v4); acc4(acc, v5); acc4(acc, v6); acc4(acc, v7);
    }
    if (i + 4 <= e) {
        int a0 = __ldg(&g_csr[i]);     int a1 = __ldg(&g_csr[i + 1]);
        int a2 = __ldg(&g_csr[i + 2]); int a3 = __ldg(&g_csr[i + 3]);
        float4 v0 = __ldcg(&x4[a0 * 16 + q]);
        float4 v1 = __ldcg(&x4[a1 * 16 + q]);
        float4 v2 = __ldcg(&x4[a2 * 16 + q]);
        float4 v3 = __ldcg(&x4[a3 * 16 + q]);
        acc4(acc, v0); acc4(acc, v1); acc4(acc, v2); acc4(acc, v3);
        i += 4;
    }
    for (; i < e; i++) {
        int s0 = __ldg(&g_csr[i]);
        float4 v = __ldcg(&x4[s0 * 16 + q]);
        acc4(acc, v);
    }
    int deg = e - s;
    float invd = 1.0f / (float)(deg > 0 ? deg : 1);
    acc.x *= invd; acc.y *= invd; acc.z *= invd; acc.w *= invd;
    return acc;
}

// ---------------- producer: gather one 64-node tile into buf (128 threads) ----------------
__device__ __forceinline__ void gather_tile(const float* __restrict__ xin,
                                            int tile, int lid, float* buf) {
    int node0 = tile * TILE_N;
    int ln = lid >> 4, q = lid & 15;
    const float4* x4 = (const float4*)xin;
#pragma unroll
    for (int sub = 0; sub < 8; sub++) {
        int n = sub * 8 + ln;
        int node = node0 + n;
        float4 agg = make_float4(0.f, 0.f, 0.f, 0.f);
        float4 xv = agg;
        if (node < N_NODES) {
            agg = gather_mean(x4, node, q);
            xv = __ldcg(&x4[node * 16 + q]);
        }
        *(float4*)&buf[n * SROW + q * 4] = agg;
        *(float4*)&buf[n * SROW + 64 + q * 4] = xv;
    }
}

// ---------------- consumer: GEMM one tile from buf (128 threads, 4n x 8f) ----------------
template <bool FINAL>
__device__ __forceinline__ void gemm_tile(
    const float* __restrict__ Wlg,   // [64][64]
    const float* __restrict__ Wrg,   // [64][64]
    const float* __restrict__ Wog,   // [64][16] (FINAL)
    const float* __restrict__ bl,
    const float* __restrict__ bout,
    float* __restrict__ dst,
    int tile, int lid, float* buf) {
    int node0 = tile * TILE_N;
    int f0 = (lid & 7) * 8;
    int ngrp = lid >> 3;
    const float* r0 = &buf[(ngrp * 4 + 0) * SROW];
    const float* r1 = r0 + SROW;
    const float* r2 = r0 + 2 * SROW;
    const float* r3 = r0 + 3 * SROW;

    float4 bA, bB;
    bA.x = __ldg(&bl[f0]);     bA.y = __ldg(&bl[f0 + 1]);
    bA.z = __ldg(&bl[f0 + 2]); bA.w = __ldg(&bl[f0 + 3]);
    bB.x = __ldg(&bl[f0 + 4]); bB.y = __ldg(&bl[f0 + 5]);
    bB.z = __ldg(&bl[f0 + 6]); bB.w = __ldg(&bl[f0 + 7]);
    float4 aA0 = bA, aA1 = bA, aA2 = bA, aA3 = bA;
    float4 aB0 = bB, aB1 = bB, aB2 = bB, aB3 = bB;

    // half 1: agg @ Wl (buf offset 0)
#pragma unroll 4
    for (int k4 = 0; k4 < 16; k4++) {
        float4 a0 = *(const float4*)&r0[k4 * 4];
        float4 a1 = *(const float4*)&r1[k4 * 4];
        float4 a2 = *(const float4*)&r2[k4 * 4];
        float4 a3 = *(const float4*)&r3[k4 * 4];
#pragma unroll
        for (int kk = 0; kk < 4; kk++) {
            const float* wr = &Wlg[(k4 * 4 + kk) * 64 + f0];
            float4 wA = __ldg((const float4*)&wr[0]);
            float4 wB = __ldg((const float4*)&wr[4]);
            float s0 = (&a0.x)[kk], s1 = (&a1.x)[kk], s2 = (&a2.x)[kk], s3 = (&a3.x)[kk];
            aA0 = fma4(s0, wA, aA0); aB0 = fma4(s0, wB, aB0);
            aA1 = fma4(s1, wA, aA1); aB1 = fma4(s1, wB, aB1);
            aA2 = fma4(s2, wA, aA2); aB2 = fma4(s2, wB, aB2);
            aA3 = fma4(s3, wA, aA3); aB3 = fma4(s3, wB, aB3);
        }
    }
    // half 2: x @ Wr (buf offset 64)
#pragma unroll 4
    for (int k4 = 0; k4 < 16; k4++) {
        float4 a0 = *(const float4*)&r0[64 + k4 * 4];
        float4 a1 = *(const float4*)&r1[64 + k4 * 4];
        float4 a2 = *(const float4*)&r2[64 + k4 * 4];
        float4 a3 = *(const float4*)&r3[64 + k4 * 4];
#pragma unroll
        for (int kk = 0; kk < 4; kk++) {
            const float* wr = &Wrg[(k4 * 4 + kk) * 64 + f0];
            float4 wA = __ldg((const float4*)&wr[0]);
            float4 wB = __ldg((const float4*)&wr[4]);
            float s0 = (&a0.x)[kk], s1 = (&a1.x)[kk], s2 = (&a2.x)[kk], s3 = (&a3.x)[kk];
            aA0 = fma4(s0, wA, aA0); aB0 = fma4(s0, wB, aB0);
            aA1 = fma4(s1, wA, aA1); aB1 = fma4(s1, wB, aB1);
            aA2 = fma4(s2, wA, aA2); aB2 = fma4(s2, wB, aB2);
            aA3 = fma4(s3, wA, aA3); aB3 = fma4(s3, wB, aB3);
        }
    }
    aA0 = relu4(aA0); aA1 = relu4(aA1); aA2 = relu4(aA2); aA3 = relu4(aA3);
    aB0 = relu4(aB0); aB1 = relu4(aB1); aB2 = relu4(aB2); aB3 = relu4(aB3);

    int nb = ngrp * 4;
    if (!FINAL) {
        int gn = node0 + nb;
        if (gn + 0 < N_NODES) {
            *(float4*)&dst[(gn + 0) * 64 + f0] = aA0;
            *(float4*)&dst[(gn + 0) * 64 + f0 + 4] = aB0;
        }
        if (gn + 1 < N_NODES) {
            *(float4*)&dst[(gn + 1) * 64 + f0] = aA1;
            *(float4*)&dst[(gn + 1) * 64 + f0 + 4] = aB1;
        }
        if (gn + 2 < N_NODES) {
            *(float4*)&dst[(gn + 2) * 64 + f0] = aA2;
            *(float4*)&dst[(gn + 2) * 64 + f0 + 4] = aB2;
        }
        if (gn + 3 < N_NODES) {
            *(float4*)&dst[(gn + 3) * 64 + f0] = aA3;
            *(float4*)&dst[(gn + 3) * 64 + f0 + 4] = aB3;
        }
    } else {
        // consumer-only barrier: all GEMM reads of buf done before overwrite
        asm volatile("bar.sync 1, 128;" ::: "memory");
        *(float4*)&buf[(nb + 0) * SROW + f0] = aA0;
        *(float4*)&buf[(nb + 0) * SROW + f0 + 4] = aB0;
        *(float4*)&buf[(nb + 1) * SROW + f0] = aA1;
        *(float4*)&buf[(nb + 1) * SROW + f0 + 4] = aB1;
        *(float4*)&buf[(nb + 2) * SROW + f0] = aA2;
        *(float4*)&buf[(nb + 2) * SROW + f0 + 4] = aB2;
        *(float4*)&buf[(nb + 3) * SROW + f0] = aA3;
        *(float4*)&buf[(nb + 3) * SROW + f0 + 4] = aB3;
        asm volatile("bar.sync 1, 128;" ::: "memory");
        // output projection: n = lid>>1 (0..63), o0 = (lid&1)*8
        int n = lid >> 1;
        int o0 = (lid & 1) * 8;
        float4 oA, oB;
        oA.x = __ldg(&bout[o0]);     oA.y = __ldg(&bout[o0 + 1]);
        oA.z = __ldg(&bout[o0 + 2]); oA.w = __ldg(&bout[o0 + 3]);
        oB.x = __ldg(&bout[o0 + 4]); oB.y = __ldg(&bout[o0 + 5]);
        oB.z = __ldg(&bout[o0 + 6]); oB.w = __ldg(&bout[o0 + 7]);
        const float* yr = &buf[n * SROW];
#pragma unroll 4
        for (int k4 = 0; k4 < 16; k4++) {
            float4 yv = *(const float4*)&yr[k4 * 4];
#pragma unroll
            for (int kk = 0; kk < 4; kk++) {
                const float* wr = &Wog[(k4 * 4 + kk) * 16 + o0];
                float4 wA = __ldg((const float4*)&wr[0]);
                float4 wB = __ldg((const float4*)&wr[4]);
                float s = (&yv.x)[kk];
                oA = fma4(s, wA, oA);
                oB = fma4(s, wB, oB);
            }
        }
        int gn = node0 + n;
        if (gn < N_NODES) {
            *(float4*)&dst[gn * OUT_DIM + o0] = oA;
            *(float4*)&dst[gn * OUT_DIM + o0 + 4] = oB;
        }
    }
}

// ---------------- one layer: warp-specialized producer/consumer pipeline ----------------
template <bool FINAL>
__device__ __forceinline__ void run_layer(
    const float* __restrict__ xin,
    const float* __restrict__ Wlg, const float* __restrict__ Wrg,
    const float* __restrict__ Wog,
    const float* __restrict__ bl, const float* __restrict__ bout,
    float* __restrict__ dst,
    int b, int tid, float* buf0, float* buf1) {
    bool prod = tid < 128;
    int lid = prod ? tid : tid - 128;
    int t0 = b;
    if (t0 < NTILES && prod) gather_tile(xin, t0, lid, buf0);
    __syncthreads();
    for (int i = 0;; i++) {
        int tc = t0 + i * NBLK;
        if (tc >= NTILES) break;
        float* bufc = (i & 1) ? buf1 : buf0;
        float* bufp = (i & 1) ? buf0 : buf1;
        if (prod) {
            int tp = tc + NBLK;
            if (tp < NTILES) gather_tile(xin, tp, lid, bufp);
        } else {
            gemm_tile<FINAL>(Wlg, Wrg, Wog, bl, bout, dst, tc, lid, bufc);
        }
        __syncthreads();
    }
}

// ---------------- persistent kernel ----------------
__global__ void __launch_bounds__(TPB, 3) fused_kernel(
    const float* __restrict__ x, const int* __restrict__ ei,
    const float* __restrict__ Wl, const float* __restrict__ bl,
    const float* __restrict__ Wr, const float* __restrict__ Wout,
    const float* __restrict__ bout, float* __restrict__ out) {
    extern __shared__ float smem[];
    float* buf0 = smem;                 // 64*132 floats
    float* buf1 = smem + TILE_N * SROW;
    __shared__ int sInts[8];

    int tid = threadIdx.x;
    int b = blockIdx.x;
    int gtid = b * TPB + tid;
    int lane = tid & 31, w = tid >> 5;

    // phase 0: zero counts
    for (int i = gtid; i < N_NODES; i += GSTRIDE) g_count[i] = 0;
    grid_barrier();

    // phase 1: histogram
    {
        const int4* dst4 = (const int4*)(ei + N_EDGES);
        for (int t = gtid; t < N_EDGES / 4; t += GSTRIDE) {
            int4 d = __ldg(&dst4[t]);
            atomicAdd(&g_count[d.x], 1);
            atomicAdd(&g_count[d.y], 1);
            atomicAdd(&g_count[d.z], 1);
            atomicAdd(&g_count[d.w], 1);
        }
    }
    grid_barrier();

    // phase 2a: block-local exclusive scan of CHUNK counts
    {
        int base = b * CHUNK;
        int idx = base + tid;
        int v = (tid < CHUNK && idx < N_NODES) ? g_count[idx] : 0;
        int s = v;
#pragma unroll
        for (int d = 1; d < 32; d <<= 1) {
            int tv = __shfl_up_sync(0xffffffffu, s, d);
            if (lane >= d) s += tv;
        }
        if (lane == 31) sInts[w] = s;
        __syncthreads();
        if (tid == 0) {
            int acc = 0;
#pragma unroll
            for (int k = 0; k < 8; k++) { int t2 = sInts[k]; sInts[k] = acc; acc += t2; }
        }
        __syncthreads();
        int incl = s + sInts[w];
        if (tid < CHUNK && idx < N_NODES) g_off[idx] = incl - v;
        if (tid == TPB - 1) g_blocksum[b] = incl;
    }
    grid_barrier();

    // phase 2b: block 0 scans the NBLK block sums (2 per thread)
    if (b == 0) {
        int base2 = tid * 2;
        int v0 = (base2 + 0 < NBLK) ? g_blocksum[base2 + 0] : 0;
        int v1 = (base2 + 1 < NBLK) ? g_blocksum[base2 + 1] : 0;
        int tsum = v0 + v1;
        int s = tsum;
#pragma unroll
        for (int d = 1; d < 32; d <<= 1) {
            int tv = __shfl_up_sync(0xffffffffu, s, d);
            if (lane >= d) s += tv;
        }
        if (lane == 31) sInts[w] = s;
        __syncthreads();
        if (tid == 0) {
            int acc = 0;
#pragma unroll
            for (int k = 0; k < 8; k++) { int t2 = sInts[k]; sInts[k] = acc; acc += t2; }
        }
        __syncthreads();
        int excl = (s - tsum) + sInts[w];
        if (base2 + 0 < NBLK) g_blockoff[base2 + 0] = excl;
        if (base2 + 1 < NBLK) g_blockoff[base2 + 1] = excl + v0;
    }
    grid_barrier();

    // phase 2c: add block offsets; init fill cursors
    {
        int off = g_blockoff[b];
        int idx = b * CHUNK + tid;
        if (tid < CHUNK && idx < N_NODES) {
            int o = g_off[idx] + off;
            g_off[idx] = o;
            g_count[idx] = o;
        }
        if (gtid == 0) g_off[N_NODES] = N_EDGES;
    }
    grid_barrier();

    // phase 3: fill CSR
    {
        const int4* src4 = (const int4*)ei;
        const int4* dst4 = (const int4*)(ei + N_EDGES);
        for (int t = gtid; t < N_EDGES / 4; t += GSTRIDE) {
            int4 sv = __ldg(&src4[t]);
            int4 d = __ldg(&dst4[t]);
            g_csr[atomicAdd(&g_count[d.x], 1)] = sv.x;
            g_csr[atomicAdd(&g_count[d.y], 1)] = sv.y;
            g_csr[atomicAdd(&g_count[d.z], 1)] = sv.z;
            g_csr[atomicAdd(&g_count[d.w], 1)] = sv.w;
        }
    }
    grid_barrier();

    // ---- layer 1: x -> g_h0 ----
    run_layer<false>(x, Wl, Wr, Wout, bl, bout, g_h0, b, tid, buf0, buf1);
    grid_barrier();

    // ---- layer 2: g_h0 -> g_h1 ----
    run_layer<false>(g_h0, Wl + 4096, Wr + 4096, Wout,
                     bl + HIDDEN, bout, g_h1, b, tid, buf0, buf1);
    grid_barrier();

    // ---- layer 3 + output projection: g_h1 -> out ----
    run_layer<true>(g_h1, Wl + 8192, Wr + 8192, Wout,
                    bl + 2 * HIDDEN, bout, out, b, tid, buf0, buf1);
}

extern "C" void kernel_launch(void* const* d_in, const int* in_sizes, int n_in,
                              void* d_out, int out_size) {
    const float* x = (const float*)d_in[0];
    const int* ei = (const int*)d_in[1];
    const float* Wl = (const float*)d_in[2];
    const float* bl = (const float*)d_in[3];
    const float* Wr = (const float*)d_in[4];
    const float* Wout = (const float*)d_in[5];
    const float* bout = (const float*)d_in[6];
    float* out = (float*)d_out;

    const int SMEM_BYTES = 2 * TILE_N * SROW * 4;  // 67.6 KB
    static int configured = 0;
    if (!configured) {
        cudaFuncSetAttribute(fused_kernel,
                             cudaFuncAttributeMaxDynamicSharedMemorySize, SMEM_BYTES);
        configured = 1;
    }
    fused_kernel<<<NBLK, TPB, SMEM_BYTES>>>(x, ei, Wl, bl, Wr, Wout, bout, out);
}

// round 13
// speedup vs baseline: 1.5320x; 1.5320x over previous
#include <cuda_runtime.h>
#include <cuda_fp16.h>

#define N_NODES 50000
#define N_EDGES 800000
#define HIDDEN 64
#define OUT_DIM 16
#define NBLK 592          // 4 blocks/SM x 148 SMs
#define TPB 256
#define GSTRIDE (NBLK * TPB)
#define CHUNK 85          // ceil(50000/592)
#define TILE_N 64
#define NTILES 782        // ceil(50000/64)
#define SROW 132          // padded feature row: 128 data + 4 pad

// ---------------- device scratch ----------------
__device__ int g_count[N_NODES];
__device__ int g_off[N_NODES + 1];
__device__ int g_csr[N_EDGES];
__device__ int g_blocksum[NBLK];
__device__ int g_blockoff[NBLK];
__device__ unsigned g_bar_cnt;
__device__ unsigned g_bar_gen;
__device__ __align__(16) __half g_hx[N_NODES * HIDDEN];  // fp16 copy of input x
__device__ __align__(16) __half g_h0[N_NODES * HIDDEN];  // fp16 hidden
__device__ __align__(16) __half g_h1[N_NODES * HIDDEN];

// ---------------- software grid barrier ----------------
__device__ __forceinline__ void grid_barrier() {
    __syncthreads();
    if (threadIdx.x == 0) {
        unsigned gen = *((volatile unsigned*)&g_bar_gen);
        __threadfence();
        unsigned a = atomicAdd(&g_bar_cnt, 1u);
        if (a == NBLK - 1) {
            g_bar_cnt = 0;
            __threadfence();
            atomicExch(&g_bar_gen, gen + 1u);
        } else {
            while (*((volatile unsigned*)&g_bar_gen) == gen) { __nanosleep(32); }
        }
        __threadfence();
    }
    __syncthreads();
}

__device__ __forceinline__ float4 fma4(float s, float4 w, float4 acc) {
    acc.x = fmaf(s, w.x, acc.x);
    acc.y = fmaf(s, w.y, acc.y);
    acc.z = fmaf(s, w.z, acc.z);
    acc.w = fmaf(s, w.w, acc.w);
    return acc;
}
__device__ __forceinline__ float4 relu4(float4 v) {
    v.x = fmaxf(v.x, 0.f); v.y = fmaxf(v.y, 0.f);
    v.z = fmaxf(v.z, 0.f); v.w = fmaxf(v.w, 0.f);
    return v;
}
// accumulate 8 halves (uint4) into two float4s
__device__ __forceinline__ void acc_h8(float4& lo, float4& hi, uint4 v) {
    __half2* h = (__half2*)&v;
    float2 f0 = __half22float2(h[0]);
    float2 f1 = __half22float2(h[1]);
    float2 f2 = __half22float2(h[2]);
    float2 f3 = __half22float2(h[3]);
    lo.x += f0.x; lo.y += f0.y; lo.z += f1.x; lo.w += f1.y;
    hi.x += f2.x; hi.y += f2.y; hi.z += f3.x; hi.w += f3.y;
}
__device__ __forceinline__ uint2 f4_to_h4(float4 a) {
    __half2 lo = __floats2half2_rn(a.x, a.y);
    __half2 hi = __floats2half2_rn(a.z, a.w);
    uint2 r;
    r.x = *(unsigned*)&lo;
    r.y = *(unsigned*)&hi;
    return r;
}

// ---------------- one 64-node tile ----------------
// xin: fp16 rows (64 halves = 128B). Gather: 8 threads/node, each owns 8 halves.
template <bool FINAL>
__device__ __forceinline__ void layer_tile(
    const __half* __restrict__ xin,
    const float* __restrict__ Wlg,   // [64][64]
    const float* __restrict__ Wrg,   // [64][64]
    const float* __restrict__ Wog,   // [64][16] (FINAL)
    const float* __restrict__ bl,
    const float* __restrict__ bout,
    void* __restrict__ dst,          // __half* (!FINAL) or float* (FINAL)
    int tile, int tid, float* sFeat) {
    int node0 = tile * TILE_N;
    // gather: 2 sub-rounds of 32 nodes; sFeat[n][0:64]=agg(fp32), [64:128]=x(fp32)
    {
        int ln = tid >> 3, q = tid & 7;              // 32 nodes, 8 threads each
        const uint4* x8 = (const uint4*)xin;         // row = 8 uint4
#pragma unroll
        for (int sub = 0; sub < 2; sub++) {
            int n = sub * 32 + ln;
            int node = node0 + n;
            float4 aLo = make_float4(0.f, 0.f, 0.f, 0.f);
            float4 aHi = aLo;
            float4 xLo = aLo, xHi = aLo;
            if (node < N_NODES) {
                int s = __ldg(&g_off[node]);
                int e = __ldg(&g_off[node + 1]);
                int i = s;
                int i0 = 0, i1 = 0, i2 = 0, i3 = 0;
                if (i + 4 <= e) {
                    i0 = __ldg(&g_csr[i]);     i1 = __ldg(&g_csr[i + 1]);
                    i2 = __ldg(&g_csr[i + 2]); i3 = __ldg(&g_csr[i + 3]);
                }
                while (i + 4 <= e) {
                    uint4 v0 = __ldg(&x8[i0 * 8 + q]);
                    uint4 v1 = __ldg(&x8[i1 * 8 + q]);
                    uint4 v2 = __ldg(&x8[i2 * 8 + q]);
                    uint4 v3 = __ldg(&x8[i3 * 8 + q]);
                    i += 4;
                    if (i + 4 <= e) {
                        i0 = __ldg(&g_csr[i]);     i1 = __ldg(&g_csr[i + 1]);
                        i2 = __ldg(&g_csr[i + 2]); i3 = __ldg(&g_csr[i + 3]);
                    }
                    acc_h8(aLo, aHi, v0); acc_h8(aLo, aHi, v1);
                    acc_h8(aLo, aHi, v2); acc_h8(aLo, aHi, v3);
                }
                for (; i < e; i++) {
                    int s0 = __ldg(&g_csr[i]);
                    uint4 v = __ldg(&x8[s0 * 8 + q]);
                    acc_h8(aLo, aHi, v);
                }
                int deg = e - s;
                float invd = 1.0f / (float)(deg > 0 ? deg : 1);
                aLo.x *= invd; aLo.y *= invd; aLo.z *= invd; aLo.w *= invd;
                aHi.x *= invd; aHi.y *= invd; aHi.z *= invd; aHi.w *= invd;
                uint4 xv = __ldg(&x8[node * 8 + q]);
                float4 z = make_float4(0.f, 0.f, 0.f, 0.f);
                xLo = z; xHi = z;
                acc_h8(xLo, xHi, xv);
            }
            *(float4*)&sFeat[n * SROW + q * 8] = aLo;
            *(float4*)&sFeat[n * SROW + q * 8 + 4] = aHi;
            *(float4*)&sFeat[n * SROW + 64 + q * 8] = xLo;
            *(float4*)&sFeat[n * SROW + 64 + q * 8 + 4] = xHi;
        }
    }
    __syncthreads();

    // GEMM: 4 nodes x 4 features per thread (R8-proven shape), K=128 from sFeat
    int f0 = (tid & 15) * 4;
    int ngrp = tid >> 4;
    const float* r0 = &sFeat[(ngrp * 4 + 0) * SROW];
    const float* r1 = r0 + SROW;
    const float* r2 = r0 + 2 * SROW;
    const float* r3 = r0 + 3 * SROW;

    float4 bias;
    bias.x = __ldg(&bl[f0]); bias.y = __ldg(&bl[f0 + 1]);
    bias.z = __ldg(&bl[f0 + 2]); bias.w = __ldg(&bl[f0 + 3]);
    float4 acc0 = bias, acc1 = bias, acc2 = bias, acc3 = bias;

    // half 1: agg @ Wl (sFeat offset 0)
#pragma unroll 4
    for (int k4 = 0; k4 < 16; k4++) {
        float4 a0 = *(const float4*)&r0[k4 * 4];
        float4 a1 = *(const float4*)&r1[k4 * 4];
        float4 a2 = *(const float4*)&r2[k4 * 4];
        float4 a3 = *(const float4*)&r3[k4 * 4];
        const float* wb = &Wlg[k4 * 256 + f0];
        float4 w0 = __ldg((const float4*)&wb[0]);
        float4 w1 = __ldg((const float4*)&wb[64]);
        float4 w2 = __ldg((const float4*)&wb[128]);
        float4 w3 = __ldg((const float4*)&wb[192]);
        acc0 = fma4(a0.x, w0, acc0); acc0 = fma4(a0.y, w1, acc0);
        acc0 = fma4(a0.z, w2, acc0); acc0 = fma4(a0.w, w3, acc0);
        acc1 = fma4(a1.x, w0, acc1); acc1 = fma4(a1.y, w1, acc1);
        acc1 = fma4(a1.z, w2, acc1); acc1 = fma4(a1.w, w3, acc1);
        acc2 = fma4(a2.x, w0, acc2); acc2 = fma4(a2.y, w1, acc2);
        acc2 = fma4(a2.z, w2, acc2); acc2 = fma4(a2.w, w3, acc2);
        acc3 = fma4(a3.x, w0, acc3); acc3 = fma4(a3.y, w1, acc3);
        acc3 = fma4(a3.z, w2, acc3); acc3 = fma4(a3.w, w3, acc3);
    }
    // half 2: x @ Wr (sFeat offset 64)
#pragma unroll 4
    for (int k4 = 0; k4 < 16; k4++) {
        float4 a0 = *(const float4*)&r0[64 + k4 * 4];
        float4 a1 = *(const float4*)&r1[64 + k4 * 4];
        float4 a2 = *(const float4*)&r2[64 + k4 * 4];
        float4 a3 = *(const float4*)&r3[64 + k4 * 4];
        const float* wb = &Wrg[k4 * 256 + f0];
        float4 w0 = __ldg((const float4*)&wb[0]);
        float4 w1 = __ldg((const float4*)&wb[64]);
        float4 w2 = __ldg((const float4*)&wb[128]);
        float4 w3 = __ldg((const float4*)&wb[192]);
        acc0 = fma4(a0.x, w0, acc0); acc0 = fma4(a0.y, w1, acc0);
        acc0 = fma4(a0.z, w2, acc0); acc0 = fma4(a0.w, w3, acc0);
        acc1 = fma4(a1.x, w0, acc1); acc1 = fma4(a1.y, w1, acc1);
        acc1 = fma4(a1.z, w2, acc1); acc1 = fma4(a1.w, w3, acc1);
        acc2 = fma4(a2.x, w0, acc2); acc2 = fma4(a2.y, w1, acc2);
        acc2 = fma4(a2.z, w2, acc2); acc2 = fma4(a2.w, w3, acc2);
        acc3 = fma4(a3.x, w0, acc3); acc3 = fma4(a3.y, w1, acc3);
        acc3 = fma4(a3.z, w2, acc3); acc3 = fma4(a3.w, w3, acc3);
    }
    acc0 = relu4(acc0); acc1 = relu4(acc1); acc2 = relu4(acc2); acc3 = relu4(acc3);

    int nb = ngrp * 4;
    if (!FINAL) {
        __half* dh = (__half*)dst;
        int gn = node0 + nb;
        if (gn + 0 < N_NODES) *(uint2*)&dh[(gn + 0) * 64 + f0] = f4_to_h4(acc0);
        if (gn + 1 < N_NODES) *(uint2*)&dh[(gn + 1) * 64 + f0] = f4_to_h4(acc1);
        if (gn + 2 < N_NODES) *(uint2*)&dh[(gn + 2) * 64 + f0] = f4_to_h4(acc2);
        if (gn + 3 < N_NODES) *(uint2*)&dh[(gn + 3) * 64 + f0] = f4_to_h4(acc3);
        __syncthreads();
    } else {
        float* df = (float*)dst;
        __syncthreads();
        *(float4*)&sFeat[(nb + 0) * SROW + f0] = acc0;
        *(float4*)&sFeat[(nb + 1) * SROW + f0] = acc1;
        *(float4*)&sFeat[(nb + 2) * SROW + f0] = acc2;
        *(float4*)&sFeat[(nb + 3) * SROW + f0] = acc3;
        __syncthreads();
        int n = tid >> 2;
        int o0 = (tid & 3) * 4;
        float4 oacc;
        oacc.x = __ldg(&bout[o0]); oacc.y = __ldg(&bout[o0 + 1]);
        oacc.z = __ldg(&bout[o0 + 2]); oacc.w = __ldg(&bout[o0 + 3]);
        const float* yr = &sFeat[n * SROW];
#pragma unroll 4
        for (int k4 = 0; k4 < 16; k4++) {
            float4 yv = *(const float4*)&yr[k4 * 4];
            const float* wb = &Wog[k4 * 64 + o0];
            float4 w0 = __ldg((const float4*)&wb[0]);
            float4 w1 = __ldg((const float4*)&wb[16]);
            float4 w2 = __ldg((const float4*)&wb[32]);
            float4 w3 = __ldg((const float4*)&wb[48]);
            oacc = fma4(yv.x, w0, oacc); oacc = fma4(yv.y, w1, oacc);
            oacc = fma4(yv.z, w2, oacc); oacc = fma4(yv.w, w3, oacc);
        }
        int gn = node0 + n;
        if (gn < N_NODES) *(float4*)&df[gn * OUT_DIM + o0] = oacc;
        __syncthreads();
    }
}

// ---------------- persistent kernel ----------------
__global__ void __launch_bounds__(TPB, 4) fused_kernel(
    const float* __restrict__ x, const int* __restrict__ ei,
    const float* __restrict__ Wl, const float* __restrict__ bl,
    const float* __restrict__ Wr, const float* __restrict__ Wout,
    const float* __restrict__ bout, float* __restrict__ out) {
    __shared__ float sFeat[TILE_N * SROW];   // 33.8 KB
    __shared__ int sInts[8];

    int tid = threadIdx.x;
    int b = blockIdx.x;
    int gtid = b * TPB + tid;
    int lane = tid & 31, w = tid >> 5;

    // phase 0: zero counts + convert x to fp16
    for (int i = gtid; i < N_NODES; i += GSTRIDE) g_count[i] = 0;
    {
        const float4* x4 = (const float4*)x;
        uint2* hx = (uint2*)g_hx;
        for (int i = gtid; i < N_NODES * HIDDEN / 4; i += GSTRIDE) {
            float4 v = __ldg(&x4[i]);
            hx[i] = f4_to_h4(v);
        }
    }
    grid_barrier();

    // phase 1: histogram
    {
        const int4* dst4 = (const int4*)(ei + N_EDGES);
        for (int t = gtid; t < N_EDGES / 4; t += GSTRIDE) {
            int4 d = __ldg(&dst4[t]);
            atomicAdd(&g_count[d.x], 1);
            atomicAdd(&g_count[d.y], 1);
            atomicAdd(&g_count[d.z], 1);
            atomicAdd(&g_count[d.w], 1);
        }
    }
    grid_barrier();

    // phase 2a: block-local exclusive scan of CHUNK counts
    {
        int base = b * CHUNK;
        int idx = base + tid;
        int v = (tid < CHUNK && idx < N_NODES) ? g_count[idx] : 0;
        int s = v;
#pragma unroll
        for (int d = 1; d < 32; d <<= 1) {
            int tv = __shfl_up_sync(0xffffffffu, s, d);
            if (lane >= d) s += tv;
        }
        if (lane == 31) sInts[w] = s;
        __syncthreads();
        if (tid == 0) {
            int acc = 0;
#pragma unroll
            for (int k = 0; k < 8; k++) { int t2 = sInts[k]; sInts[k] = acc; acc += t2; }
        }
        __syncthreads();
        int incl = s + sInts[w];
        if (tid < CHUNK && idx < N_NODES) g_off[idx] = incl - v;
        if (tid == TPB - 1) g_blocksum[b] = incl;
    }
    grid_barrier();

    // phase 2b: block 0 scans the NBLK block sums (3 per thread)
    if (b == 0) {
        int base2 = tid * 3;
        int v0 = (base2 + 0 < NBLK) ? g_blocksum[base2 + 0] : 0;
        int v1 = (base2 + 1 < NBLK) ? g_blocksum[base2 + 1] : 0;
        int v2 = (base2 + 2 < NBLK) ? g_blocksum[base2 + 2] : 0;
        int tsum = v0 + v1 + v2;
        int s = tsum;
#pragma unroll
        for (int d = 1; d < 32; d <<= 1) {
            int tv = __shfl_up_sync(0xffffffffu, s, d);
            if (lane >= d) s += tv;
        }
        if (lane == 31) sInts[w] = s;
        __syncthreads();
        if (tid == 0) {
            int acc = 0;
#pragma unroll
            for (int k = 0; k < 8; k++) { int t2 = sInts[k]; sInts[k] = acc; acc += t2; }
        }
        __syncthreads();
        int excl = (s - tsum) + sInts[w];
        if (base2 + 0 < NBLK) { g_blockoff[base2 + 0] = excl; excl += v0; }
        if (base2 + 1 < NBLK) { g_blockoff[base2 + 1] = excl; excl += v1; }
        if (base2 + 2 < NBLK) { g_blockoff[base2 + 2] = excl; excl += v2; }
    }
    grid_barrier();

    // phase 2c: add block offsets; init fill cursors
    {
        int off = g_blockoff[b];
        int idx = b * CHUNK + tid;
        if (tid < CHUNK && idx < N_NODES) {
            int o = g_off[idx] + off;
            g_off[idx] = o;
            g_count[idx] = o;
        }
        if (gtid == 0) g_off[N_NODES] = N_EDGES;
    }
    grid_barrier();

    // phase 3: fill CSR
    {
        const int4* src4 = (const int4*)ei;
        const int4* dst4 = (const int4*)(ei + N_EDGES);
        for (int t = gtid; t < N_EDGES / 4; t += GSTRIDE) {
            int4 sv = __ldg(&src4[t]);
            int4 d = __ldg(&dst4[t]);
            g_csr[atomicAdd(&g_count[d.x], 1)] = sv.x;
            g_csr[atomicAdd(&g_count[d.y], 1)] = sv.y;
            g_csr[atomicAdd(&g_count[d.z], 1)] = sv.z;
            g_csr[atomicAdd(&g_count[d.w], 1)] = sv.w;
        }
    }
    grid_barrier();

    // ---- layer 1: g_hx -> g_h0 ----
    for (int tile = b; tile < NTILES; tile += NBLK)
        layer_tile<false>(g_hx, Wl, Wr, Wout, bl, bout, g_h0, tile, tid, sFeat);
    grid_barrier();

    // ---- layer 2: g_h0 -> g_h1 ----
    for (int tile = b; tile < NTILES; tile += NBLK)
        layer_tile<false>(g_h0, Wl + 4096, Wr + 4096, Wout,
                          bl + HIDDEN, bout, g_h1, tile, tid, sFeat);
    grid_barrier();

    // ---- layer 3 + output projection: g_h1 -> out ----
    for (int tile = b; tile < NTILES; tile += NBLK)
        layer_tile<true>(g_h1, Wl + 8192, Wr + 8192, Wout,
                         bl + 2 * HIDDEN, bout, out, tile, tid, sFeat);
}

extern "C" void kernel_launch(void* const* d_in, const int* in_sizes, int n_in,
                              void* d_out, int out_size) {
    const float* x = (const float*)d_in[0];
    const int* ei = (const int*)d_in[1];
    const float* Wl = (const float*)d_in[2];
    const float* bl = (const float*)d_in[3];
    const float* Wr = (const float*)d_in[4];
    const float* Wout = (const float*)d_in[5];
    const float* bout = (const float*)d_in[6];
    float* out = (float*)d_out;

    fused_kernel<<<NBLK, TPB>>>(x, ei, Wl, bl, Wr, Wout, bout, out);
}

// round 14
// speedup vs baseline: 1.6861x; 1.1006x over previous
#include <cuda_runtime.h>
#include <cuda_fp16.h>
#include <mma.h>

using namespace nvcuda;

#define N_NODES 50000
#define N_EDGES 800000
#define HIDDEN 64
#define OUT_DIM 16
#define NBLK 592          // 4 blocks/SM x 148 SMs
#define TPB 256
#define GSTRIDE (NBLK * TPB)
#define CHUNK 85          // ceil(50000/592)
#define TILE_N 64
#define NTILES 782        // ceil(50000/64)
#define AROW 136          // sA row stride in halves (128 + 8 pad; mult of 8)
#define CROW 68           // sC row stride in floats (64 + 4 pad; mult of 4)

// ---------------- device scratch ----------------
__device__ int g_count[N_NODES];
__device__ int g_off[N_NODES + 1];
__device__ int g_csr[N_EDGES];
__device__ int g_blocksum[NBLK];
__device__ int g_blockoff[NBLK];
__device__ unsigned g_bar_cnt;
__device__ unsigned g_bar_gen;
__device__ __align__(16) __half g_hx[N_NODES * HIDDEN];   // fp16 input x
__device__ __align__(16) __half g_h0[N_NODES * HIDDEN];   // fp16 hidden
__device__ __align__(16) __half g_h1[N_NODES * HIDDEN];
__device__ __align__(16) __half g_wh[3 * 128 * 64];       // fp16 [layer][k 0..127][f]; k<64 Wl, k>=64 Wr

// ---------------- software grid barrier ----------------
__device__ __forceinline__ void grid_barrier() {
    __syncthreads();
    if (threadIdx.x == 0) {
        unsigned gen = *((volatile unsigned*)&g_bar_gen);
        __threadfence();
        unsigned a = atomicAdd(&g_bar_cnt, 1u);
        if (a == NBLK - 1) {
            g_bar_cnt = 0;
            __threadfence();
            atomicExch(&g_bar_gen, gen + 1u);
        } else {
            while (*((volatile unsigned*)&g_bar_gen) == gen) { __nanosleep(32); }
        }
        __threadfence();
    }
    __syncthreads();
}

__device__ __forceinline__ float4 fma4(float s, float4 w, float4 acc) {
    acc.x = fmaf(s, w.x, acc.x);
    acc.y = fmaf(s, w.y, acc.y);
    acc.z = fmaf(s, w.z, acc.z);
    acc.w = fmaf(s, w.w, acc.w);
    return acc;
}
// accumulate 8 halves (uint4) into two float4s
__device__ __forceinline__ void acc_h8(float4& lo, float4& hi, uint4 v) {
    __half2* h = (__half2*)&v;
    float2 f0 = __half22float2(h[0]);
    float2 f1 = __half22float2(h[1]);
    float2 f2 = __half22float2(h[2]);
    float2 f3 = __half22float2(h[3]);
    lo.x += f0.x; lo.y += f0.y; lo.z += f1.x; lo.w += f1.y;
    hi.x += f2.x; hi.y += f2.y; hi.z += f3.x; hi.w += f3.y;
}
__device__ __forceinline__ uint2 f4_to_h4(float4 a) {
    __half2 lo = __floats2half2_rn(a.x, a.y);
    __half2 hi = __floats2half2_rn(a.z, a.w);
    uint2 r;
    r.x = *(unsigned*)&lo;
    r.y = *(unsigned*)&hi;
    return r;
}

// ---------------- one 64-node tile: fp16 gather -> wmma GEMM -> epilogue ----------------
template <bool FINAL>
__device__ __forceinline__ void layer_tile(
    const __half* __restrict__ xin,
    const __half* __restrict__ whL,  // fp16 [128][64] for this layer
    const float* __restrict__ Wog,   // [64][16] (FINAL)
    const float* __restrict__ bl,
    const float* __restrict__ bout,
    void* __restrict__ dst,          // __half* (!FINAL) or float* (FINAL)
    int tile, int tid, __half* sA, float* sC) {
    int node0 = tile * TILE_N;
    // ---- gather (fp32 accumulate, fp16 store): 8 threads/node, 2 sub-rounds ----
    {
        int ln = tid >> 3, q = tid & 7;
        const uint4* x8 = (const uint4*)xin;
#pragma unroll
        for (int sub = 0; sub < 2; sub++) {
            int n = sub * 32 + ln;
            int node = node0 + n;
            float4 aLo = make_float4(0.f, 0.f, 0.f, 0.f);
            float4 aHi = aLo;
            uint4 xv = make_uint4(0u, 0u, 0u, 0u);
            if (node < N_NODES) {
                int s = __ldg(&g_off[node]);
                int e = __ldg(&g_off[node + 1]);
                int i = s;
                int i0 = 0, i1 = 0, i2 = 0, i3 = 0;
                if (i + 4 <= e) {
                    i0 = __ldg(&g_csr[i]);     i1 = __ldg(&g_csr[i + 1]);
                    i2 = __ldg(&g_csr[i + 2]); i3 = __ldg(&g_csr[i + 3]);
                }
                while (i + 4 <= e) {
                    uint4 v0 = __ldg(&x8[i0 * 8 + q]);
                    uint4 v1 = __ldg(&x8[i1 * 8 + q]);
                    uint4 v2 = __ldg(&x8[i2 * 8 + q]);
                    uint4 v3 = __ldg(&x8[i3 * 8 + q]);
                    i += 4;
                    if (i + 4 <= e) {
                        i0 = __ldg(&g_csr[i]);     i1 = __ldg(&g_csr[i + 1]);
                        i2 = __ldg(&g_csr[i + 2]); i3 = __ldg(&g_csr[i + 3]);
                    }
                    acc_h8(aLo, aHi, v0); acc_h8(aLo, aHi, v1);
                    acc_h8(aLo, aHi, v2); acc_h8(aLo, aHi, v3);
                }
                for (; i < e; i++) {
                    int s0 = __ldg(&g_csr[i]);
                    uint4 v = __ldg(&x8[s0 * 8 + q]);
                    acc_h8(aLo, aHi, v);
                }
                int deg = e - s;
                float invd = 1.0f / (float)(deg > 0 ? deg : 1);
                aLo.x *= invd; aLo.y *= invd; aLo.z *= invd; aLo.w *= invd;
                aHi.x *= invd; aHi.y *= invd; aHi.z *= invd; aHi.w *= invd;
                xv = __ldg(&x8[node * 8 + q]);
            }
            uint2 hLo = f4_to_h4(aLo);
            uint2 hHi = f4_to_h4(aHi);
            uint4 hA = make_uint4(hLo.x, hLo.y, hHi.x, hHi.y);
            *(uint4*)&sA[n * AROW + q * 8] = hA;          // agg halves [q*8 .. q*8+7]
            *(uint4*)&sA[n * AROW + 64 + q * 8] = xv;     // x halves (raw fp16)
        }
    }
    __syncthreads();

    // ---- wmma GEMM: C[64][64] = sA[64][128] @ whL[128][64], fp32 accumulate ----
    {
        int wid = tid >> 5;                 // 0..7
        int rowblk = wid >> 1;              // 0..3 (16 nodes each)
        int colblk0 = (wid & 1) * 2;        // 0 or 2; this warp does colblk0, colblk0+1
        wmma::fragment<wmma::accumulator, 16, 16, 16, float> c0, c1;
        wmma::fill_fragment(c0, 0.0f);
        wmma::fill_fragment(c1, 0.0f);
#pragma unroll
        for (int k = 0; k < 8; k++) {
            wmma::fragment<wmma::matrix_a, 16, 16, 16, __half, wmma::row_major> af;
            wmma::load_matrix_sync(af, sA + rowblk * 16 * AROW + k * 16, AROW);
            wmma::fragment<wmma::matrix_b, 16, 16, 16, __half, wmma::row_major> b0, b1;
            wmma::load_matrix_sync(b0, whL + k * 16 * 64 + colblk0 * 16, 64);
            wmma::load_matrix_sync(b1, whL + k * 16 * 64 + (colblk0 + 1) * 16, 64);
            wmma::mma_sync(c0, af, b0, c0);
            wmma::mma_sync(c1, af, b1, c1);
        }
        wmma::store_matrix_sync(sC + rowblk * 16 * CROW + colblk0 * 16, c0, CROW,
                                wmma::mem_row_major);
        wmma::store_matrix_sync(sC + rowblk * 16 * CROW + (colblk0 + 1) * 16, c1, CROW,
                                wmma::mem_row_major);
    }
    __syncthreads();

    // ---- epilogue: bias + relu ----
    int n = tid >> 2;
    int f0 = (tid & 3) * 16;
    float4 y[4];
    {
        const float* cr = &sC[n * CROW + f0];
#pragma unroll
        for (int j = 0; j < 4; j++) {
            float4 v = *(const float4*)&cr[j * 4];
            float4 bb;
            bb.x = __ldg(&bl[f0 + j * 4]);     bb.y = __ldg(&bl[f0 + j * 4 + 1]);
            bb.z = __ldg(&bl[f0 + j * 4 + 2]); bb.w = __ldg(&bl[f0 + j * 4 + 3]);
            v.x = fmaxf(v.x + bb.x, 0.f); v.y = fmaxf(v.y + bb.y, 0.f);
            v.z = fmaxf(v.z + bb.z, 0.f); v.w = fmaxf(v.w + bb.w, 0.f);
            y[j] = v;
        }
    }
    int gn = node0 + n;
    if (!FINAL) {
        if (gn < N_NODES) {
            __half* dh = (__half*)dst;
            uint2 h0 = f4_to_h4(y[0]);
            uint2 h1 = f4_to_h4(y[1]);
            uint2 h2 = f4_to_h4(y[2]);
            uint2 h3 = f4_to_h4(y[3]);
            *(uint4*)&dh[gn * 64 + f0] = make_uint4(h0.x, h0.y, h1.x, h1.y);
            *(uint4*)&dh[gn * 64 + f0 + 8] = make_uint4(h2.x, h2.y, h3.x, h3.y);
        }
        __syncthreads();   // protect sA/sC before next tile
    } else {
        // write relu'd y back into sC (each thread owns exactly these cells)
        float* cr = &sC[n * CROW + f0];
#pragma unroll
        for (int j = 0; j < 4; j++) *(float4*)&cr[j * 4] = y[j];
        __syncthreads();
        // output projection: n2 = tid>>2 (0..63), o0 = (tid&3)*4
        int n2 = tid >> 2;
        int o0 = (tid & 3) * 4;
        float4 oacc;
        oacc.x = __ldg(&bout[o0]); oacc.y = __ldg(&bout[o0 + 1]);
        oacc.z = __ldg(&bout[o0 + 2]); oacc.w = __ldg(&bout[o0 + 3]);
        const float* yr = &sC[n2 * CROW];
#pragma unroll 4
        for (int k4 = 0; k4 < 16; k4++) {
            float4 yv = *(const float4*)&yr[k4 * 4];
            const float* wb = &Wog[k4 * 64 + o0];
            float4 w0 = __ldg((const float4*)&wb[0]);
            float4 w1 = __ldg((const float4*)&wb[16]);
            float4 w2 = __ldg((const float4*)&wb[32]);
            float4 w3 = __ldg((const float4*)&wb[48]);
            oacc = fma4(yv.x, w0, oacc); oacc = fma4(yv.y, w1, oacc);
            oacc = fma4(yv.z, w2, oacc); oacc = fma4(yv.w, w3, oacc);
        }
        int gn2 = node0 + n2;
        if (gn2 < N_NODES) *(float4*)&((float*)dst)[gn2 * OUT_DIM + o0] = oacc;
        __syncthreads();
    }
}

// ---------------- persistent kernel ----------------
__global__ void __launch_bounds__(TPB, 4) fused_kernel(
    const float* __restrict__ x, const int* __restrict__ ei,
    const float* __restrict__ Wl, const float* __restrict__ bl,
    const float* __restrict__ Wr, const float* __restrict__ Wout,
    const float* __restrict__ bout, float* __restrict__ out) {
    __shared__ __half sA[TILE_N * AROW];   // 17.0 KB
    __shared__ float sC[TILE_N * CROW];    // 17.0 KB
    __shared__ int sInts[8];

    int tid = threadIdx.x;
    int b = blockIdx.x;
    int gtid = b * TPB + tid;
    int lane = tid & 31, w = tid >> 5;

    // phase 0: zero counts + convert x and weights to fp16
    for (int i = gtid; i < N_NODES; i += GSTRIDE) g_count[i] = 0;
    {
        const float4* x4 = (const float4*)x;
        uint2* hx = (uint2*)g_hx;
        for (int i = gtid; i < N_NODES * HIDDEN / 4; i += GSTRIDE) {
            float4 v = __ldg(&x4[i]);
            hx[i] = f4_to_h4(v);
        }
        // g_wh[l][k][f]: k<64 -> Wl[l][k][f], k>=64 -> Wr[l][k-64][f]
        for (int i = gtid; i < 3 * 128 * 64; i += GSTRIDE) {
            int l = i / 8192;
            int r = i - l * 8192;
            int k = r >> 6;
            int f = r & 63;
            float v = (k < 64) ? __ldg(&Wl[l * 4096 + k * 64 + f])
                               : __ldg(&Wr[l * 4096 + (k - 64) * 64 + f]);
            g_wh[i] = __float2half_rn(v);
        }
    }
    grid_barrier();

    // phase 1: histogram
    {
        const int4* dst4 = (const int4*)(ei + N_EDGES);
        for (int t = gtid; t < N_EDGES / 4; t += GSTRIDE) {
            int4 d = __ldg(&dst4[t]);
            atomicAdd(&g_count[d.x], 1);
            atomicAdd(&g_count[d.y], 1);
            atomicAdd(&g_count[d.z], 1);
            atomicAdd(&g_count[d.w], 1);
        }
    }
    grid_barrier();

    // phase 2a: block-local exclusive scan of CHUNK counts
    {
        int base = b * CHUNK;
        int idx = base + tid;
        int v = (tid < CHUNK && idx < N_NODES) ? g_count[idx] : 0;
        int s = v;
#pragma unroll
        for (int d = 1; d < 32; d <<= 1) {
            int tv = __shfl_up_sync(0xffffffffu, s, d);
            if (lane >= d) s += tv;
        }
        if (lane == 31) sInts[w] = s;
        __syncthreads();
        if (tid == 0) {
            int acc = 0;
#pragma unroll
            for (int k = 0; k < 8; k++) { int t2 = sInts[k]; sInts[k] = acc; acc += t2; }
        }
        __syncthreads();
        int incl = s + sInts[w];
        if (tid < CHUNK && idx < N_NODES) g_off[idx] = incl - v;
        if (tid == TPB - 1) g_blocksum[b] = incl;
    }
    grid_barrier();

    // phase 2b: block 0 scans the NBLK block sums (3 per thread)
    if (b == 0) {
        int base2 = tid * 3;
        int v0 = (base2 + 0 < NBLK) ? g_blocksum[base2 + 0] : 0;
        int v1 = (base2 + 1 < NBLK) ? g_blocksum[base2 + 1] : 0;
        int v2 = (base2 + 2 < NBLK) ? g_blocksum[base2 + 2] : 0;
        int tsum = v0 + v1 + v2;
        int s = tsum;
#pragma unroll
        for (int d = 1; d < 32; d <<= 1) {
            int tv = __shfl_up_sync(0xffffffffu, s, d);
            if (lane >= d) s += tv;
        }
        if (lane == 31) sInts[w] = s;
        __syncthreads();
        if (tid == 0) {
            int acc = 0;
#pragma unroll
            for (int k = 0; k < 8; k++) { int t2 = sInts[k]; sInts[k] = acc; acc += t2; }
        }
        __syncthreads();
        int excl = (s - tsum) + sInts[w];
        if (base2 + 0 < NBLK) { g_blockoff[base2 + 0] = excl; excl += v0; }
        if (base2 + 1 < NBLK) { g_blockoff[base2 + 1] = excl; excl += v1; }
        if (base2 + 2 < NBLK) { g_blockoff[base2 + 2] = excl; excl += v2; }
    }
    grid_barrier();

    // phase 2c: add block offsets; init fill cursors
    {
        int off = g_blockoff[b];
        int idx = b * CHUNK + tid;
        if (tid < CHUNK && idx < N_NODES) {
            int o = g_off[idx] + off;
            g_off[idx] = o;
            g_count[idx] = o;
        }
        if (gtid == 0) g_off[N_NODES] = N_EDGES;
    }
    grid_barrier();

    // phase 3: fill CSR
    {
        const int4* src4 = (const int4*)ei;
        const int4* dst4 = (const int4*)(ei + N_EDGES);
        for (int t = gtid; t < N_EDGES / 4; t += GSTRIDE) {
            int4 sv = __ldg(&src4[t]);
            int4 d = __ldg(&dst4[t]);
            g_csr[atomicAdd(&g_count[d.x], 1)] = sv.x;
            g_csr[atomicAdd(&g_count[d.y], 1)] = sv.y;
            g_csr[atomicAdd(&g_count[d.z], 1)] = sv.z;
            g_csr[atomicAdd(&g_count[d.w], 1)] = sv.w;
        }
    }
    grid_barrier();

    // ---- layer 1: g_hx -> g_h0 ----
    for (int tile = b; tile < NTILES; tile += NBLK)
        layer_tile<false>(g_hx, g_wh, Wout, bl, bout, g_h0, tile, tid, sA, sC);
    grid_barrier();

    // ---- layer 2: g_h0 -> g_h1 ----
    for (int tile = b; tile < NTILES; tile += NBLK)
        layer_tile<false>(g_h0, g_wh + 8192, Wout, bl + HIDDEN, bout, g_h1,
                          tile, tid, sA, sC);
    grid_barrier();

    // ---- layer 3 + output projection: g_h1 -> out ----
    for (int tile = b; tile < NTILES; tile += NBLK)
        layer_tile<true>(g_h1, g_wh + 16384, Wout, bl + 2 * HIDDEN, bout, out,
                         tile, tid, sA, sC);
}

extern "C" void kernel_launch(void* const* d_in, const int* in_sizes, int n_in,
                              void* d_out, int out_size) {
    const float* x = (const float*)d_in[0];
    const int* ei = (const int*)d_in[1];
    const float* Wl = (const float*)d_in[2];
    const float* bl = (const float*)d_in[3];
    const float* Wr = (const float*)d_in[4];
    const float* Wout = (const float*)d_in[5];
    const float* bout = (const float*)d_in[6];
    float* out = (float*)d_out;

    fused_kernel<<<NBLK, TPB>>>(x, ei, Wl, bl, Wr, Wout, bout, out);
}